// round 8
// baseline (speedup 1.0000x reference)
#include <cuda_runtime.h>
#include <cstdint>

#define NSUB  64
#define NPTS  65536
#define TPB   128         // 4 warps; warp owns 64 of the tile's 256 points
#define TILES 8           // 256-pt tiles per CTA
#define GRIDX 12          // slots per subdomain = GRIDX*TILES*256 = 24576 (expected ~18500)
#define STR   68          // smem row stride (floats): conflict-free frag access
#define RWIN  0.1328125f  // 8.5/64 — PoU window radius (tail < 4e-6)

// Static device scratch (no allocation).
__device__ float    g_u[NSUB * NPTS];
__device__ uint32_t gBW[2][NSUB][64 * STR];   // tf32 weights, [k*STR + n] = W[n][k]
__device__ int      g_bin_cnt[64];
__device__ int      g_bin_idx[64][NPTS];

// ---------------------------------------------------------------------------
// Scalar helpers
// ---------------------------------------------------------------------------
__device__ __forceinline__ float tanh_hw(float x) {
    float r; asm("tanh.approx.f32 %0, %1;" : "=f"(r) : "f"(x)); return r;
}
__device__ __forceinline__ float tanh_acc(float x) {
    float e; asm("ex2.approx.f32 %0, %1;" : "=f"(e) : "f"(x * 2.8853900817779268f));
    float r; asm("rcp.approx.f32 %0, %1;" : "=f"(r) : "f"(e + 1.0f));
    return fmaf(-2.0f, r, 1.0f);
}
__device__ __forceinline__ uint32_t f2tf32(float f) {
    uint32_t r; asm("cvt.rna.tf32.f32 %0, %1;" : "=r"(r) : "f"(f)); return r;
}

// PoU bin window — single definition shared by MLP (writer) and reduce (reader).
__device__ __forceinline__ void window_of(int s, int& lo, int& hi) {
    const float c = (float)s * (1.0f / 63.0f);
    int l = (int)floorf((c - RWIN) * 64.0f);
    int h = (int)floorf((c + RWIN) * 64.0f);
    lo = l < 0 ? 0 : l;
    hi = h > 63 ? 63 : h;
}
__device__ __forceinline__ int bin_of(float x) {
    int b = (int)(x * 64.0f);
    return b < 0 ? 0 : (b > 63 ? 63 : b);
}

// mma.sync m16n8k8 tf32 (baseline PTX, tensor pipe)
__device__ __forceinline__ void mma8(float& d0, float& d1, float& d2, float& d3,
                                     uint32_t a0, uint32_t a1, uint32_t a2, uint32_t a3,
                                     uint32_t b0, uint32_t b1) {
    asm volatile(
        "mma.sync.aligned.m16n8k8.row.col.f32.tf32.tf32.f32 "
        "{%0,%1,%2,%3}, {%4,%5,%6,%7}, {%8,%9}, {%0,%1,%2,%3};"
        : "+f"(d0), "+f"(d1), "+f"(d2), "+f"(d3)
        : "r"(a0), "r"(a1), "r"(a2), "r"(a3), "r"(b0), "r"(b1));
}

// ---------------------------------------------------------------------------
// Prep: coalesced-write gather transpose (incl. zeroing the 4 pad cols).
// ---------------------------------------------------------------------------
__global__ void prep_weights(const float* __restrict__ W1,
                             const float* __restrict__ W2) {
    const int i = blockIdx.x * 256 + threadIdx.x;      // over 2*64*4352
    if (i >= 2 * NSUB * 64 * STR) return;
    const int l = i / (NSUB * 64 * STR);
    const int r = i - l * (NSUB * 64 * STR);
    const int s = r / (64 * STR);
    const int j = r - s * (64 * STR);
    const int k = j / STR, n = j - k * STR;
    const float* W = l ? W2 : W1;
    gBW[l][s][j] = (n < 64) ? f2tf32(W[s * 4096 + n * 64 + k]) : 0u;
}
__global__ void zero_counters() { g_bin_cnt[threadIdx.x] = 0; }
__global__ void bin_points(const float* __restrict__ X) {
    const int n = blockIdx.x * 256 + threadIdx.x;
    const int b = bin_of(X[n]);
    const int p = atomicAdd(&g_bin_cnt[b], 1);
    g_bin_idx[b][p] = n;
}

// ---------------------------------------------------------------------------
// Shared memory (~106 KB -> 2 CTAs/SM)
// ---------------------------------------------------------------------------
struct __align__(16) SMem {
    uint32_t B1[64 * STR];
    uint32_t B2[64 * STR];
    uint32_t H[4][64 * STR];       // per-warp activations (64 rows/warp)
    float w0[64], b0[64], b1[64], b2[64], w3[64];
    float b3;
    int cum[24];
};

__device__ __forceinline__ int slot_to_n(const int* __restrict__ cum, int nb,
                                         int lo, int slot) {
    int j = 0;
#pragma unroll 1
    while (j + 1 < nb && slot >= cum[j + 1]) j++;
    return g_bin_idx[lo + j][slot - cum[j]];
}

// ---------------------------------------------------------------------------
// Main kernel. Fragment maps (m16n8k8, g = lane>>2, t = lane&3), 4 m-tiles:
//   mt covers rows g+16mt (c0,c1) and g+8+16mt (c2,c3); warp = 64 rows.
// grid = (GRIDX, NSUB); CTA covers TILES x 256 slots of s's window list.
// ---------------------------------------------------------------------------
__global__ __launch_bounds__(TPB, 2)
void fbpinn_mlp(const float* __restrict__ X,
                const float* __restrict__ W0g, const float* __restrict__ B0g,
                const float* __restrict__ B1g, const float* __restrict__ B2g,
                const float* __restrict__ W3g, const float* __restrict__ B3g) {
    extern __shared__ char smraw[];
    SMem* sm = (SMem*)smraw;

    const int s    = blockIdx.y;
    const int tid  = threadIdx.x;
    const int wid  = tid >> 5;
    const int lane = tid & 31;
    const int g    = lane >> 2;
    const int t    = lane & 3;
    const int wb   = wid * 64;

    int lo, hi;
    window_of(s, lo, hi);
    const int nb = hi - lo + 1;

    if (tid < nb) sm->cum[tid + 1] = g_bin_cnt[lo + tid];
    if (tid == 0) sm->cum[0] = 0;
    __syncthreads();
    if (tid == 0) {
        int a = 0;
#pragma unroll 1
        for (int j = 1; j <= nb; j++) { a += sm->cum[j]; sm->cum[j] = a; }
    }
    __syncthreads();
    const int total = sm->cum[nb];
    if (blockIdx.x * (TILES * 256) >= total) return;

    // cooperative smem fill
    {
        const uint4* s1 = (const uint4*)&gBW[0][s][0];
        const uint4* s2 = (const uint4*)&gBW[1][s][0];
        uint4* d1 = (uint4*)sm->B1;
        uint4* d2 = (uint4*)sm->B2;
        for (int i = tid; i < 64 * STR / 4; i += TPB) { d1[i] = s1[i]; d2[i] = s2[i]; }
        if (tid < 64) {
            sm->w0[tid] = W0g[s * 64 + tid];
            sm->b0[tid] = B0g[s * 64 + tid];
            sm->b1[tid] = B1g[s * 64 + tid];
            sm->b2[tid] = B2g[s * 64 + tid];
            sm->w3[tid] = W3g[s * 64 + tid];
        }
        if (tid == 64) sm->b3 = B3g[s];
    }
    __syncthreads();

    const float b3v = sm->b3;
    uint32_t* Hu = sm->H[wid];
    float acc[8][4][4];              // [n-tile][m-tile][c0..c3]

#pragma unroll 1
    for (int tile = 0; tile < TILES; tile++) {
        const int tb = (blockIdx.x * TILES + tile) * 256;
        if (tb >= total) break;

        // 8 rows per lane: base tb+wb+g, offsets {0,8,16,24,32,40,48,56}
        int   ni[8];
        float xv[8];
#pragma unroll
        for (int i = 0; i < 8; i++) {
            const int r = tb + wb + g + i * 8;
            if (r < total) { ni[i] = slot_to_n(sm->cum, nb, lo, r); xv[i] = X[ni[i]]; }
            else           { ni[i] = -1; xv[i] = 0.f; }
        }

        // ================= Layer 1 (A built on the fly from layer 0) ========
#pragma unroll
        for (int nt = 0; nt < 8; nt++) {
            const float2 bb = *(const float2*)&sm->b1[nt * 8 + 2 * t];
#pragma unroll
            for (int mt = 0; mt < 4; mt++) {
                acc[nt][mt][0] = bb.x; acc[nt][mt][1] = bb.y;
                acc[nt][mt][2] = bb.x; acc[nt][mt][3] = bb.y;
            }
        }
#pragma unroll
        for (int kk = 0; kk < 8; kk++) {
            const int k0 = kk * 8;
            const float wc0 = sm->w0[k0 + t],     bc0 = sm->b0[k0 + t];
            const float wc1 = sm->w0[k0 + t + 4], bc1 = sm->b0[k0 + t + 4];
            uint32_t alo[8], ahi[8];
#pragma unroll
            for (int i = 0; i < 8; i++) {
                alo[i] = f2tf32(tanh_hw(fmaf(wc0, xv[i], bc0)));
                ahi[i] = f2tf32(tanh_hw(fmaf(wc1, xv[i], bc1)));
            }
#pragma unroll
            for (int nt = 0; nt < 8; nt++) {
                const uint32_t bv0 = sm->B1[(k0 + t) * STR + nt * 8 + g];
                const uint32_t bv1 = sm->B1[(k0 + t + 4) * STR + nt * 8 + g];
#pragma unroll
                for (int mt = 0; mt < 4; mt++) {
                    mma8(acc[nt][mt][0], acc[nt][mt][1], acc[nt][mt][2], acc[nt][mt][3],
                         alo[2 * mt], alo[2 * mt + 1], ahi[2 * mt], ahi[2 * mt + 1],
                         bv0, bv1);
                }
            }
        }

        // epilogue 1: tanh -> tf32 -> per-warp H  (row = g+16mt / g+8+16mt)
        __syncwarp();
#pragma unroll
        for (int nt = 0; nt < 8; nt++) {
#pragma unroll
            for (int mt = 0; mt < 4; mt++) {
                uint2 lov, hiv;
                lov.x = f2tf32(tanh_hw(acc[nt][mt][0]));
                lov.y = f2tf32(tanh_hw(acc[nt][mt][1]));
                hiv.x = f2tf32(tanh_hw(acc[nt][mt][2]));
                hiv.y = f2tf32(tanh_hw(acc[nt][mt][3]));
                *(uint2*)&Hu[(mt * 16 + g) * STR + nt * 8 + 2 * t]     = lov;
                *(uint2*)&Hu[(mt * 16 + g + 8) * STR + nt * 8 + 2 * t] = hiv;
            }
        }
        __syncwarp();

        // ================= Layer 2 (A from H) ===============================
#pragma unroll
        for (int nt = 0; nt < 8; nt++) {
            const float2 bb = *(const float2*)&sm->b2[nt * 8 + 2 * t];
#pragma unroll
            for (int mt = 0; mt < 4; mt++) {
                acc[nt][mt][0] = bb.x; acc[nt][mt][1] = bb.y;
                acc[nt][mt][2] = bb.x; acc[nt][mt][3] = bb.y;
            }
        }
#pragma unroll
        for (int kk = 0; kk < 8; kk++) {
            const int k0 = kk * 8;
            uint32_t af[4][4];
#pragma unroll
            for (int mt = 0; mt < 4; mt++) {
                af[mt][0] = Hu[(mt * 16 + g) * STR + k0 + t];
                af[mt][1] = Hu[(mt * 16 + g + 8) * STR + k0 + t];
                af[mt][2] = Hu[(mt * 16 + g) * STR + k0 + t + 4];
                af[mt][3] = Hu[(mt * 16 + g + 8) * STR + k0 + t + 4];
            }
#pragma unroll
            for (int nt = 0; nt < 8; nt++) {
                const uint32_t bv0 = sm->B2[(k0 + t) * STR + nt * 8 + g];
                const uint32_t bv1 = sm->B2[(k0 + t + 4) * STR + nt * 8 + g];
#pragma unroll
                for (int mt = 0; mt < 4; mt++) {
                    mma8(acc[nt][mt][0], acc[nt][mt][1], acc[nt][mt][2], acc[nt][mt][3],
                         af[mt][0], af[mt][1], af[mt][2], af[mt][3], bv0, bv1);
                }
            }
        }

        // ===== output layer (fp32): u[row] = b3 + sum_n w3[n]*tanh(acc) =====
        {
            float u[8];
#pragma unroll
            for (int i = 0; i < 8; i++) u[i] = 0.f;
#pragma unroll
            for (int nt = 0; nt < 8; nt++) {
                const float2 w3p = *(const float2*)&sm->w3[nt * 8 + 2 * t];
#pragma unroll
                for (int mt = 0; mt < 4; mt++) {
                    u[2 * mt]     = fmaf(w3p.x, tanh_hw(acc[nt][mt][0]), u[2 * mt]);
                    u[2 * mt]     = fmaf(w3p.y, tanh_hw(acc[nt][mt][1]), u[2 * mt]);
                    u[2 * mt + 1] = fmaf(w3p.x, tanh_hw(acc[nt][mt][2]), u[2 * mt + 1]);
                    u[2 * mt + 1] = fmaf(w3p.y, tanh_hw(acc[nt][mt][3]), u[2 * mt + 1]);
                }
            }
#pragma unroll
            for (int d = 1; d < 4; d <<= 1) {
#pragma unroll
                for (int i = 0; i < 8; i++)
                    u[i] += __shfl_xor_sync(0xffffffffu, u[i], d);
            }
            if (t == 0) {
                float* up = g_u + s * NPTS;
                // row i=2mt+h maps to point row g + 8*(2mt+h)? No: rows are
                // g+16mt (i even) and g+8+16mt (i odd) == g + 8*i. ni[i] matches.
#pragma unroll
                for (int i = 0; i < 8; i++)
                    if (ni[i] >= 0) up[ni[i]] = u[i] + b3v;
            }
        }
    }
}

// ---------------------------------------------------------------------------
// Reduce: Gaussian PoU over the SAME window predicate + hard-BC ansatz.
// ---------------------------------------------------------------------------
__global__ __launch_bounds__(256)
void fbpinn_reduce_kernel(const float* __restrict__ X, float* __restrict__ out) {
    const int n = blockIdx.x * 256 + threadIdx.x;
    const float x = X[n];
    const int b = bin_of(x);
    const float inv_sigma = 64.0f / 1.5f;
    float num = 0.0f, den = 0.0f;
#pragma unroll 1
    for (int s = 0; s < 64; s++) {
        int lo, hi;
        window_of(s, lo, hi);
        if (b >= lo && b <= hi) {
            float tt = (x - (float)s * (1.0f / 63.0f)) * inv_sigma;
            float r = __expf(-0.5f * tt * tt);
            num = fmaf(r, g_u[s * NPTS + n], num);
            den += r;
        }
    }
    out[n] = tanh_acc(5.0f * x) * (num / den);
}

// ---------------------------------------------------------------------------
// Inputs: x, W0, b0, W1, b1, W2, b2, W3, b3. Output fp32 [65536].
// ---------------------------------------------------------------------------
extern "C" void kernel_launch(void* const* d_in, const int* in_sizes, int n_in,
                              void* d_out, int out_size) {
    const float* X  = (const float*)d_in[0];
    const float* W0 = (const float*)d_in[1];
    const float* B0 = (const float*)d_in[2];
    const float* W1 = (const float*)d_in[3];
    const float* B1 = (const float*)d_in[4];
    const float* W2 = (const float*)d_in[5];
    const float* B2 = (const float*)d_in[6];
    const float* W3 = (const float*)d_in[7];
    const float* B3 = (const float*)d_in[8];
    float* out = (float*)d_out;

    cudaFuncSetAttribute(fbpinn_mlp, cudaFuncAttributeMaxDynamicSharedMemorySize,
                         (int)sizeof(SMem));

    const int prep_elems = 2 * NSUB * 64 * STR;
    prep_weights<<<(prep_elems + 255) / 256, 256>>>(W1, W2);
    zero_counters<<<1, 64>>>();
    bin_points<<<NPTS / 256, 256>>>(X);
    dim3 grid(GRIDX, NSUB);
    fbpinn_mlp<<<grid, TPB, sizeof(SMem)>>>(X, W0, B0, B1, B2, W3, B3);
    fbpinn_reduce_kernel<<<NPTS / 256, 256>>>(X, out);
}

// round 9
// speedup vs baseline: 1.2463x; 1.2463x over previous
#include <cuda_runtime.h>
#include <cstdint>

#define NSUB  64
#define NPTS  65536
#define TPB   128         // 4 warps; warp owns 32 of the tile's 128 points
#define TILES 8           // 128-pt tiles per CTA
#define GRIDX 18          // slots per subdomain = GRIDX*TILES*TPB = 18432 (max ~16900)
#define STR   68          // smem row stride (floats): conflict-free frag access
#define RWIN  0.1171875f  // 7.5/64 — PoU window radius (tail < ~5e-5 rel)

// Static device scratch (no allocation).
__device__ float    g_u[NSUB * NPTS];
__device__ uint32_t gBW[2][NSUB][64 * STR];   // tf32 weights, [k*STR + n] = W[n][k]
__device__ int      g_bin_cnt[64];
__device__ int      g_bin_idx[64][NPTS];

// ---------------------------------------------------------------------------
// Scalar helpers
// ---------------------------------------------------------------------------
__device__ __forceinline__ float tanh_hw(float x) {
    float r; asm("tanh.approx.f32 %0, %1;" : "=f"(r) : "f"(x)); return r;
}
__device__ __forceinline__ float tanh_acc(float x) {
    float e; asm("ex2.approx.f32 %0, %1;" : "=f"(e) : "f"(x * 2.8853900817779268f));
    float r; asm("rcp.approx.f32 %0, %1;" : "=f"(r) : "f"(e + 1.0f));
    return fmaf(-2.0f, r, 1.0f);
}
__device__ __forceinline__ uint32_t f2tf32(float f) {
    uint32_t r; asm("cvt.rna.tf32.f32 %0, %1;" : "=r"(r) : "f"(f)); return r;
}

// PoU bin window — single definition shared by MLP (writer) and reduce (reader).
__device__ __forceinline__ void window_of(int s, int& lo, int& hi) {
    const float c = (float)s * (1.0f / 63.0f);
    int l = (int)floorf((c - RWIN) * 64.0f);
    int h = (int)floorf((c + RWIN) * 64.0f);
    lo = l < 0 ? 0 : l;
    hi = h > 63 ? 63 : h;
}
__device__ __forceinline__ int bin_of(float x) {
    int b = (int)(x * 64.0f);
    return b < 0 ? 0 : (b > 63 ? 63 : b);
}

// mma.sync m16n8k8 tf32 (baseline PTX, tensor pipe)
__device__ __forceinline__ void mma8(float& d0, float& d1, float& d2, float& d3,
                                     uint32_t a0, uint32_t a1, uint32_t a2, uint32_t a3,
                                     uint32_t b0, uint32_t b1) {
    asm volatile(
        "mma.sync.aligned.m16n8k8.row.col.f32.tf32.tf32.f32 "
        "{%0,%1,%2,%3}, {%4,%5,%6,%7}, {%8,%9}, {%0,%1,%2,%3};"
        : "+f"(d0), "+f"(d1), "+f"(d2), "+f"(d3)
        : "r"(a0), "r"(a1), "r"(a2), "r"(a3), "r"(b0), "r"(b1));
}

// ---------------------------------------------------------------------------
// Prep: coalesced-write gather transpose (incl. zeroing the 4 pad cols).
// ---------------------------------------------------------------------------
__global__ void prep_weights(const float* __restrict__ W1,
                             const float* __restrict__ W2) {
    const int i = blockIdx.x * 256 + threadIdx.x;      // over 2*64*64*STR
    if (i >= 2 * NSUB * 64 * STR) return;
    const int l = i / (NSUB * 64 * STR);
    const int r = i - l * (NSUB * 64 * STR);
    const int s = r / (64 * STR);
    const int j = r - s * (64 * STR);
    const int k = j / STR, n = j - k * STR;
    const float* W = l ? W2 : W1;
    gBW[l][s][j] = (n < 64) ? f2tf32(W[s * 4096 + n * 64 + k]) : 0u;
}
__global__ void zero_counters() { g_bin_cnt[threadIdx.x] = 0; }
__global__ void bin_points(const float* __restrict__ X) {
    const int n = blockIdx.x * 256 + threadIdx.x;
    const int b = bin_of(X[n]);
    const int p = atomicAdd(&g_bin_cnt[b], 1);
    g_bin_idx[b][p] = n;
}

// ---------------------------------------------------------------------------
// Shared memory (~71 KB -> 3 CTAs/SM, reg-limited too: 156*128*3 < 64K)
// ---------------------------------------------------------------------------
struct __align__(16) SMem {
    uint32_t B1[64 * STR];
    uint32_t B2[64 * STR];
    uint32_t H[4][32 * STR];       // per-warp activations
    float w0[64], b0[64], b1[64], b2[64], w3[64];
    float b3;
    int cum[24];                   // bin prefix sums (nb <= 16)
};

__device__ __forceinline__ int slot_to_n(const int* __restrict__ cum, int nb,
                                         int lo, int slot) {
    int j = 0;
#pragma unroll 1
    while (j + 1 < nb && slot >= cum[j + 1]) j++;
    return g_bin_idx[lo + j][slot - cum[j]];
}

// ---------------------------------------------------------------------------
// Main kernel. Fragment maps (PTX ISA m16n8k8, g = lane>>2, t = lane&3):
//   A: a0=(g,t) a1=(g+8,t) a2=(g,t+4) a3=(g+8,t+4)
//   B: b0=(k=t,n=g) b1=(k=t+4,n=g)
//   D: c0=(g,2t) c1=(g,2t+1) c2=(g+8,2t) c3=(g+8,2t+1)
// grid = (GRIDX, NSUB): CTA covers slots [bx*1024, bx*1024+1024) of s's window.
// ---------------------------------------------------------------------------
__global__ __launch_bounds__(TPB, 3)
void fbpinn_mlp(const float* __restrict__ X,
                const float* __restrict__ W0g, const float* __restrict__ B0g,
                const float* __restrict__ B1g, const float* __restrict__ B2g,
                const float* __restrict__ W3g, const float* __restrict__ B3g) {
    extern __shared__ char smraw[];
    SMem* sm = (SMem*)smraw;

    const int s    = blockIdx.y;
    const int tid  = threadIdx.x;
    const int wid  = tid >> 5;
    const int lane = tid & 31;
    const int g    = lane >> 2;
    const int t    = lane & 3;
    const int wb   = wid * 32;

    int lo, hi;
    window_of(s, lo, hi);
    const int nb = hi - lo + 1;

    if (tid < nb) sm->cum[tid + 1] = g_bin_cnt[lo + tid];
    if (tid == 0) sm->cum[0] = 0;
    __syncthreads();
    if (tid == 0) {
        int a = 0;
#pragma unroll 1
        for (int j = 1; j <= nb; j++) { a += sm->cum[j]; sm->cum[j] = a; }
    }
    __syncthreads();
    const int total = sm->cum[nb];
    if (blockIdx.x * (TILES * TPB) >= total) return;

    // cooperative smem fill
    {
        const uint4* s1 = (const uint4*)&gBW[0][s][0];
        const uint4* s2 = (const uint4*)&gBW[1][s][0];
        uint4* d1 = (uint4*)sm->B1;
        uint4* d2 = (uint4*)sm->B2;
        for (int i = tid; i < 64 * STR / 4; i += TPB) { d1[i] = s1[i]; d2[i] = s2[i]; }
        if (tid < 64) {
            sm->w0[tid] = W0g[s * 64 + tid];
            sm->b0[tid] = B0g[s * 64 + tid];
            sm->b1[tid] = B1g[s * 64 + tid];
            sm->b2[tid] = B2g[s * 64 + tid];
            sm->w3[tid] = W3g[s * 64 + tid];
        }
        if (tid == 64) sm->b3 = B3g[s];
    }
    __syncthreads();

    const float b3v = sm->b3;
    uint32_t* Hu = sm->H[wid];
    float acc[8][2][4];

#pragma unroll 1
    for (int tile = 0; tile < TILES; tile++) {
        const int tb = (blockIdx.x * TILES + tile) * TPB;
        if (tb >= total) break;

        const int r0 = tb + wb + g, r1 = r0 + 8, r2 = r0 + 16, r3 = r0 + 24;
        int n0 = -1, n1 = -1, n2 = -1, n3 = -1;
        float x0 = 0.f, x1 = 0.f, x2 = 0.f, x3 = 0.f;
        if (r0 < total) { n0 = slot_to_n(sm->cum, nb, lo, r0); x0 = X[n0]; }
        if (r1 < total) { n1 = slot_to_n(sm->cum, nb, lo, r1); x1 = X[n1]; }
        if (r2 < total) { n2 = slot_to_n(sm->cum, nb, lo, r2); x2 = X[n2]; }
        if (r3 < total) { n3 = slot_to_n(sm->cum, nb, lo, r3); x3 = X[n3]; }

        // ================= Layer 1 (A built on the fly from layer 0) ========
#pragma unroll
        for (int nt = 0; nt < 8; nt++) {
            const float2 bb = *(const float2*)&sm->b1[nt * 8 + 2 * t];
#pragma unroll
            for (int mt = 0; mt < 2; mt++) {
                acc[nt][mt][0] = bb.x; acc[nt][mt][1] = bb.y;
                acc[nt][mt][2] = bb.x; acc[nt][mt][3] = bb.y;
            }
        }
#pragma unroll
        for (int kk = 0; kk < 8; kk++) {
            const int k0 = kk * 8;
            const float wc0 = sm->w0[k0 + t],     bc0 = sm->b0[k0 + t];
            const float wc1 = sm->w0[k0 + t + 4], bc1 = sm->b0[k0 + t + 4];
            uint32_t a0[4], a1[4];
            a0[0] = f2tf32(tanh_hw(fmaf(wc0, x0, bc0)));
            a0[1] = f2tf32(tanh_hw(fmaf(wc0, x1, bc0)));
            a0[2] = f2tf32(tanh_hw(fmaf(wc1, x0, bc1)));
            a0[3] = f2tf32(tanh_hw(fmaf(wc1, x1, bc1)));
            a1[0] = f2tf32(tanh_hw(fmaf(wc0, x2, bc0)));
            a1[1] = f2tf32(tanh_hw(fmaf(wc0, x3, bc0)));
            a1[2] = f2tf32(tanh_hw(fmaf(wc1, x2, bc1)));
            a1[3] = f2tf32(tanh_hw(fmaf(wc1, x3, bc1)));
#pragma unroll
            for (int nt = 0; nt < 8; nt++) {
                const uint32_t bv0 = sm->B1[(k0 + t) * STR + nt * 8 + g];
                const uint32_t bv1 = sm->B1[(k0 + t + 4) * STR + nt * 8 + g];
                mma8(acc[nt][0][0], acc[nt][0][1], acc[nt][0][2], acc[nt][0][3],
                     a0[0], a0[1], a0[2], a0[3], bv0, bv1);
                mma8(acc[nt][1][0], acc[nt][1][1], acc[nt][1][2], acc[nt][1][3],
                     a1[0], a1[1], a1[2], a1[3], bv0, bv1);
            }
        }

        // epilogue 1: tanh -> tf32 -> per-warp H
        __syncwarp();
#pragma unroll
        for (int nt = 0; nt < 8; nt++) {
#pragma unroll
            for (int mt = 0; mt < 2; mt++) {
                uint2 lov, hiv;
                lov.x = f2tf32(tanh_hw(acc[nt][mt][0]));
                lov.y = f2tf32(tanh_hw(acc[nt][mt][1]));
                hiv.x = f2tf32(tanh_hw(acc[nt][mt][2]));
                hiv.y = f2tf32(tanh_hw(acc[nt][mt][3]));
                *(uint2*)&Hu[(mt * 16 + g) * STR + nt * 8 + 2 * t]     = lov;
                *(uint2*)&Hu[(mt * 16 + g + 8) * STR + nt * 8 + 2 * t] = hiv;
            }
        }
        __syncwarp();

        // ================= Layer 2 (A from H) ===============================
#pragma unroll
        for (int nt = 0; nt < 8; nt++) {
            const float2 bb = *(const float2*)&sm->b2[nt * 8 + 2 * t];
#pragma unroll
            for (int mt = 0; mt < 2; mt++) {
                acc[nt][mt][0] = bb.x; acc[nt][mt][1] = bb.y;
                acc[nt][mt][2] = bb.x; acc[nt][mt][3] = bb.y;
            }
        }
#pragma unroll
        for (int kk = 0; kk < 8; kk++) {
            const int k0 = kk * 8;
            uint32_t a0[4], a1[4];
            a0[0] = Hu[(g) * STR + k0 + t];
            a0[1] = Hu[(g + 8) * STR + k0 + t];
            a0[2] = Hu[(g) * STR + k0 + t + 4];
            a0[3] = Hu[(g + 8) * STR + k0 + t + 4];
            a1[0] = Hu[(g + 16) * STR + k0 + t];
            a1[1] = Hu[(g + 24) * STR + k0 + t];
            a1[2] = Hu[(g + 16) * STR + k0 + t + 4];
            a1[3] = Hu[(g + 24) * STR + k0 + t + 4];
#pragma unroll
            for (int nt = 0; nt < 8; nt++) {
                const uint32_t bv0 = sm->B2[(k0 + t) * STR + nt * 8 + g];
                const uint32_t bv1 = sm->B2[(k0 + t + 4) * STR + nt * 8 + g];
                mma8(acc[nt][0][0], acc[nt][0][1], acc[nt][0][2], acc[nt][0][3],
                     a0[0], a0[1], a0[2], a0[3], bv0, bv1);
                mma8(acc[nt][1][0], acc[nt][1][1], acc[nt][1][2], acc[nt][1][3],
                     a1[0], a1[1], a1[2], a1[3], bv0, bv1);
            }
        }

        // ===== output layer (fp32): u[row] = b3 + sum_n w3[n]*tanh(acc) =====
        {
            float u0 = 0.f, u1 = 0.f, u2 = 0.f, u3 = 0.f;
#pragma unroll
            for (int nt = 0; nt < 8; nt++) {
                const float2 w3p = *(const float2*)&sm->w3[nt * 8 + 2 * t];
                u0 = fmaf(w3p.x, tanh_hw(acc[nt][0][0]), u0);
                u0 = fmaf(w3p.y, tanh_hw(acc[nt][0][1]), u0);
                u1 = fmaf(w3p.x, tanh_hw(acc[nt][0][2]), u1);
                u1 = fmaf(w3p.y, tanh_hw(acc[nt][0][3]), u1);
                u2 = fmaf(w3p.x, tanh_hw(acc[nt][1][0]), u2);
                u2 = fmaf(w3p.y, tanh_hw(acc[nt][1][1]), u2);
                u3 = fmaf(w3p.x, tanh_hw(acc[nt][1][2]), u3);
                u3 = fmaf(w3p.y, tanh_hw(acc[nt][1][3]), u3);
            }
#pragma unroll
            for (int d = 1; d < 4; d <<= 1) {
                u0 += __shfl_xor_sync(0xffffffffu, u0, d);
                u1 += __shfl_xor_sync(0xffffffffu, u1, d);
                u2 += __shfl_xor_sync(0xffffffffu, u2, d);
                u3 += __shfl_xor_sync(0xffffffffu, u3, d);
            }
            if (t == 0) {
                float* up = g_u + s * NPTS;
                if (n0 >= 0) up[n0] = u0 + b3v;
                if (n1 >= 0) up[n1] = u1 + b3v;
                if (n2 >= 0) up[n2] = u2 + b3v;
                if (n3 >= 0) up[n3] = u3 + b3v;
            }
        }
    }
}

// ---------------------------------------------------------------------------
// Reduce: Gaussian PoU over the SAME window predicate + hard-BC ansatz.
// ---------------------------------------------------------------------------
__global__ __launch_bounds__(256)
void fbpinn_reduce_kernel(const float* __restrict__ X, float* __restrict__ out) {
    const int n = blockIdx.x * 256 + threadIdx.x;
    const float x = X[n];
    const int b = bin_of(x);
    const float inv_sigma = 64.0f / 1.5f;
    float num = 0.0f, den = 0.0f;
#pragma unroll 1
    for (int s = 0; s < 64; s++) {
        int lo, hi;
        window_of(s, lo, hi);
        if (b >= lo && b <= hi) {
            float tt = (x - (float)s * (1.0f / 63.0f)) * inv_sigma;
            float r = __expf(-0.5f * tt * tt);
            num = fmaf(r, g_u[s * NPTS + n], num);
            den += r;
        }
    }
    out[n] = tanh_acc(5.0f * x) * (num / den);
}

// ---------------------------------------------------------------------------
// Inputs: x, W0, b0, W1, b1, W2, b2, W3, b3. Output fp32 [65536].
// ---------------------------------------------------------------------------
extern "C" void kernel_launch(void* const* d_in, const int* in_sizes, int n_in,
                              void* d_out, int out_size) {
    const float* X  = (const float*)d_in[0];
    const float* W0 = (const float*)d_in[1];
    const float* B0 = (const float*)d_in[2];
    const float* W1 = (const float*)d_in[3];
    const float* B1 = (const float*)d_in[4];
    const float* W2 = (const float*)d_in[5];
    const float* B2 = (const float*)d_in[6];
    const float* W3 = (const float*)d_in[7];
    const float* B3 = (const float*)d_in[8];
    float* out = (float*)d_out;

    cudaFuncSetAttribute(fbpinn_mlp, cudaFuncAttributeMaxDynamicSharedMemorySize,
                         (int)sizeof(SMem));

    const int prep_elems = 2 * NSUB * 64 * STR;
    prep_weights<<<(prep_elems + 255) / 256, 256>>>(W1, W2);
    zero_counters<<<1, 64>>>();
    bin_points<<<NPTS / 256, 256>>>(X);
    dim3 grid(GRIDX, NSUB);
    fbpinn_mlp<<<grid, TPB, sizeof(SMem)>>>(X, W0, B0, B1, B2, W3, B3);
    fbpinn_reduce_kernel<<<NPTS / 256, 256>>>(X, out);
}

// round 10
// speedup vs baseline: 1.2956x; 1.0395x over previous
#include <cuda_runtime.h>
#include <cstdint>

#define NSUB  64
#define NPTS  65536
#define TPB   128         // 4 warps; warp owns 32 of the tile's 128 points
#define TILES 8           // 128-pt tiles per CTA
#define GRIDX 18          // slots per subdomain = 18432 (max expected ~16900)
#define STR   68          // H row stride (floats): conflict-free frag access
#define RWIN  0.1171875f  // 7.5/64 — PoU window radius (tail < ~5e-5 rel)

// Static device scratch (no allocation).
__device__ float    g_u[NSUB * NPTS];
// Fragment-packed tf32 weights: [l][s][ ((kk*4+c)*32 + lane)*4 + i ]
__device__ uint32_t gBp[2][NSUB][4096];
__device__ int      g_bin_cnt[64];
__device__ int      g_bin_idx[64][NPTS];

// ---------------------------------------------------------------------------
// Scalar helpers
// ---------------------------------------------------------------------------
__device__ __forceinline__ float tanh_hw(float x) {
    float r; asm("tanh.approx.f32 %0, %1;" : "=f"(r) : "f"(x)); return r;
}
__device__ __forceinline__ float tanh_acc(float x) {
    float e; asm("ex2.approx.f32 %0, %1;" : "=f"(e) : "f"(x * 2.8853900817779268f));
    float r; asm("rcp.approx.f32 %0, %1;" : "=f"(r) : "f"(e + 1.0f));
    return fmaf(-2.0f, r, 1.0f);
}
__device__ __forceinline__ uint32_t f2tf32(float f) {
    uint32_t r; asm("cvt.rna.tf32.f32 %0, %1;" : "=r"(r) : "f"(f)); return r;
}

// PoU bin window — single definition shared by MLP (writer) and reduce (reader).
__device__ __forceinline__ void window_of(int s, int& lo, int& hi) {
    const float c = (float)s * (1.0f / 63.0f);
    int l = (int)floorf((c - RWIN) * 64.0f);
    int h = (int)floorf((c + RWIN) * 64.0f);
    lo = l < 0 ? 0 : l;
    hi = h > 63 ? 63 : h;
}
__device__ __forceinline__ int bin_of(float x) {
    int b = (int)(x * 64.0f);
    return b < 0 ? 0 : (b > 63 ? 63 : b);
}

// mma.sync m16n8k8 tf32 (baseline PTX, tensor pipe). A operands may carry raw
// f32 bits: tf32 HMMA reads only the top 19 bits (truncation, err ~2^-11).
__device__ __forceinline__ void mma8(float& d0, float& d1, float& d2, float& d3,
                                     uint32_t a0, uint32_t a1, uint32_t a2, uint32_t a3,
                                     uint32_t b0, uint32_t b1) {
    asm volatile(
        "mma.sync.aligned.m16n8k8.row.col.f32.tf32.tf32.f32 "
        "{%0,%1,%2,%3}, {%4,%5,%6,%7}, {%8,%9}, {%0,%1,%2,%3};"
        : "+f"(d0), "+f"(d1), "+f"(d2), "+f"(d3)
        : "r"(a0), "r"(a1), "r"(a2), "r"(a3), "r"(b0), "r"(b1));
}

// ---------------------------------------------------------------------------
// Prep: fragment-packed layout.
// Per (layer l, kk, lane=(g,t)): 16 u32 = bv0[nt=0..7], bv1[nt=0..7] where
//   bv0[nt] = tf32(W[n=nt*8+g][k=kk*8+t]), bv1[nt] = tf32(W[nt*8+g][kk*8+t+4])
// stored as 4 uint4 chunks c=0..3 at u32 offset ((kk*4+c)*32+lane)*4+i.
// ---------------------------------------------------------------------------
__global__ void prep_weights(const float* __restrict__ W1,
                             const float* __restrict__ W2) {
    const int i = blockIdx.x * 256 + threadIdx.x;         // over 2*64*4096
    if (i >= 2 * NSUB * 4096) return;
    const int l  = i >> 18;            // / 262144
    const int r  = i & 262143;
    const int s  = r >> 12;            // / 4096
    const int q  = r & 4095;
    const int kk = q >> 9;             // / 512
    const int c  = (q >> 7) & 3;
    const int lane = (q >> 2) & 31;
    const int ii = q & 3;
    const int j  = c * 4 + ii;         // 0..15
    const int nt = j & 7, wh = j >> 3;
    const int g  = lane >> 2, t = lane & 3;
    const int k  = kk * 8 + t + wh * 4;
    const int n  = nt * 8 + g;
    const float* W = l ? W2 : W1;
    gBp[l][s][q] = f2tf32(W[s * 4096 + n * 64 + k]);
}
__global__ void zero_counters() { g_bin_cnt[threadIdx.x] = 0; }
__global__ void bin_points(const float* __restrict__ X) {
    const int n = blockIdx.x * 256 + threadIdx.x;
    const int b = bin_of(X[n]);
    const int p = atomicAdd(&g_bin_cnt[b], 1);
    g_bin_idx[b][p] = n;
}

// ---------------------------------------------------------------------------
// Shared memory (~69 KB -> 3 CTAs/SM; regs capped 170 by launch_bounds)
// ---------------------------------------------------------------------------
struct __align__(16) SMem {
    uint32_t Bp1[4096];            // 16 KB fragment-packed W1
    uint32_t Bp2[4096];            // 16 KB fragment-packed W2
    uint32_t H[4][32 * STR];       // per-warp activations
    float w0[64], b0[64], b1[64], b2[64], w3[64];
    float b3;
    int cum[24];
};

__device__ __forceinline__ int slot_to_n(const int* __restrict__ cum, int nb,
                                         int lo, int slot) {
    int j = 0;
#pragma unroll 1
    while (j + 1 < nb && slot >= cum[j + 1]) j++;
    return g_bin_idx[lo + j][slot - cum[j]];
}

// ---------------------------------------------------------------------------
// Main kernel. Fragment maps (m16n8k8, g = lane>>2, t = lane&3):
//   A: a0=(g,t) a1=(g+8,t) a2=(g,t+4) a3=(g+8,t+4)
//   B (packed): u0..u3 per kk -> bv0[nt], bv1[nt]
//   D: c0=(g,2t) c1=(g,2t+1) c2=(g+8,2t) c3=(g+8,2t+1)
// ---------------------------------------------------------------------------
__global__ __launch_bounds__(TPB, 3)
void fbpinn_mlp(const float* __restrict__ X,
                const float* __restrict__ W0g, const float* __restrict__ B0g,
                const float* __restrict__ B1g, const float* __restrict__ B2g,
                const float* __restrict__ W3g, const float* __restrict__ B3g) {
    extern __shared__ char smraw[];
    SMem* sm = (SMem*)smraw;

    const int s    = blockIdx.y;
    const int tid  = threadIdx.x;
    const int wid  = tid >> 5;
    const int lane = tid & 31;
    const int g    = lane >> 2;
    const int t    = lane & 3;
    const int wb   = wid * 32;

    int lo, hi;
    window_of(s, lo, hi);
    const int nb = hi - lo + 1;

    if (tid < nb) sm->cum[tid + 1] = g_bin_cnt[lo + tid];
    if (tid == 0) sm->cum[0] = 0;
    __syncthreads();
    if (tid == 0) {
        int a = 0;
#pragma unroll 1
        for (int j = 1; j <= nb; j++) { a += sm->cum[j]; sm->cum[j] = a; }
    }
    __syncthreads();
    const int total = sm->cum[nb];
    if (blockIdx.x * (TILES * TPB) >= total) return;

    // cooperative smem fill
    {
        const uint4* s1 = (const uint4*)&gBp[0][s][0];
        const uint4* s2 = (const uint4*)&gBp[1][s][0];
        uint4* d1 = (uint4*)sm->Bp1;
        uint4* d2 = (uint4*)sm->Bp2;
        for (int i = tid; i < 1024; i += TPB) { d1[i] = s1[i]; d2[i] = s2[i]; }
        if (tid < 64) {
            sm->w0[tid] = W0g[s * 64 + tid];
            sm->b0[tid] = B0g[s * 64 + tid];
            sm->b1[tid] = B1g[s * 64 + tid];
            sm->b2[tid] = B2g[s * 64 + tid];
            sm->w3[tid] = W3g[s * 64 + tid];
        }
        if (tid == 64) sm->b3 = B3g[s];
    }
    __syncthreads();

    const float b3v = sm->b3;
    uint32_t* Hu = sm->H[wid];
    const uint4* bp1 = (const uint4*)sm->Bp1;
    const uint4* bp2 = (const uint4*)sm->Bp2;
    float acc[8][2][4];

#pragma unroll 1
    for (int tile = 0; tile < TILES; tile++) {
        const int tb = (blockIdx.x * TILES + tile) * TPB;
        if (tb >= total) break;

        const int r0 = tb + wb + g, r1 = r0 + 8, r2 = r0 + 16, r3 = r0 + 24;
        int n0 = -1, n1 = -1, n2 = -1, n3 = -1;
        float x0 = 0.f, x1 = 0.f, x2 = 0.f, x3 = 0.f;
        if (r0 < total) { n0 = slot_to_n(sm->cum, nb, lo, r0); x0 = X[n0]; }
        if (r1 < total) { n1 = slot_to_n(sm->cum, nb, lo, r1); x1 = X[n1]; }
        if (r2 < total) { n2 = slot_to_n(sm->cum, nb, lo, r2); x2 = X[n2]; }
        if (r3 < total) { n3 = slot_to_n(sm->cum, nb, lo, r3); x3 = X[n3]; }

        // ================= Layer 1 (A built on the fly from layer 0) ========
#pragma unroll
        for (int nt = 0; nt < 8; nt++) {
            const float2 bb = *(const float2*)&sm->b1[nt * 8 + 2 * t];
#pragma unroll
            for (int mt = 0; mt < 2; mt++) {
                acc[nt][mt][0] = bb.x; acc[nt][mt][1] = bb.y;
                acc[nt][mt][2] = bb.x; acc[nt][mt][3] = bb.y;
            }
        }
#pragma unroll
        for (int kk = 0; kk < 8; kk++) {
            const int k0 = kk * 8;
            const float wc0 = sm->w0[k0 + t],     bc0 = sm->b0[k0 + t];
            const float wc1 = sm->w0[k0 + t + 4], bc1 = sm->b0[k0 + t + 4];
            uint32_t a0[4], a1[4];
            a0[0] = __float_as_uint(tanh_hw(fmaf(wc0, x0, bc0)));
            a0[1] = __float_as_uint(tanh_hw(fmaf(wc0, x1, bc0)));
            a0[2] = __float_as_uint(tanh_hw(fmaf(wc1, x0, bc1)));
            a0[3] = __float_as_uint(tanh_hw(fmaf(wc1, x1, bc1)));
            a1[0] = __float_as_uint(tanh_hw(fmaf(wc0, x2, bc0)));
            a1[1] = __float_as_uint(tanh_hw(fmaf(wc0, x3, bc0)));
            a1[2] = __float_as_uint(tanh_hw(fmaf(wc1, x2, bc1)));
            a1[3] = __float_as_uint(tanh_hw(fmaf(wc1, x3, bc1)));
            // packed B fragments: 4 x LDS.128, conflict-free
            const uint4 u0 = bp1[(kk * 4 + 0) * 32 + lane];
            const uint4 u1 = bp1[(kk * 4 + 1) * 32 + lane];
            const uint4 u2 = bp1[(kk * 4 + 2) * 32 + lane];
            const uint4 u3 = bp1[(kk * 4 + 3) * 32 + lane];
            const uint32_t bv0[8] = {u0.x, u0.y, u0.z, u0.w, u1.x, u1.y, u1.z, u1.w};
            const uint32_t bv1[8] = {u2.x, u2.y, u2.z, u2.w, u3.x, u3.y, u3.z, u3.w};
#pragma unroll
            for (int nt = 0; nt < 8; nt++) {
                mma8(acc[nt][0][0], acc[nt][0][1], acc[nt][0][2], acc[nt][0][3],
                     a0[0], a0[1], a0[2], a0[3], bv0[nt], bv1[nt]);
                mma8(acc[nt][1][0], acc[nt][1][1], acc[nt][1][2], acc[nt][1][3],
                     a1[0], a1[1], a1[2], a1[3], bv0[nt], bv1[nt]);
            }
        }

        // epilogue 1: tanh -> raw f32 bits -> per-warp H
        __syncwarp();
#pragma unroll
        for (int nt = 0; nt < 8; nt++) {
#pragma unroll
            for (int mt = 0; mt < 2; mt++) {
                uint2 lov, hiv;
                lov.x = __float_as_uint(tanh_hw(acc[nt][mt][0]));
                lov.y = __float_as_uint(tanh_hw(acc[nt][mt][1]));
                hiv.x = __float_as_uint(tanh_hw(acc[nt][mt][2]));
                hiv.y = __float_as_uint(tanh_hw(acc[nt][mt][3]));
                *(uint2*)&Hu[(mt * 16 + g) * STR + nt * 8 + 2 * t]     = lov;
                *(uint2*)&Hu[(mt * 16 + g + 8) * STR + nt * 8 + 2 * t] = hiv;
            }
        }
        __syncwarp();

        // ================= Layer 2 (A from H) ===============================
#pragma unroll
        for (int nt = 0; nt < 8; nt++) {
            const float2 bb = *(const float2*)&sm->b2[nt * 8 + 2 * t];
#pragma unroll
            for (int mt = 0; mt < 2; mt++) {
                acc[nt][mt][0] = bb.x; acc[nt][mt][1] = bb.y;
                acc[nt][mt][2] = bb.x; acc[nt][mt][3] = bb.y;
            }
        }
#pragma unroll
        for (int kk = 0; kk < 8; kk++) {
            const int k0 = kk * 8;
            uint32_t a0[4], a1[4];
            a0[0] = Hu[(g) * STR + k0 + t];
            a0[1] = Hu[(g + 8) * STR + k0 + t];
            a0[2] = Hu[(g) * STR + k0 + t + 4];
            a0[3] = Hu[(g + 8) * STR + k0 + t + 4];
            a1[0] = Hu[(g + 16) * STR + k0 + t];
            a1[1] = Hu[(g + 24) * STR + k0 + t];
            a1[2] = Hu[(g + 16) * STR + k0 + t + 4];
            a1[3] = Hu[(g + 24) * STR + k0 + t + 4];
            const uint4 u0 = bp2[(kk * 4 + 0) * 32 + lane];
            const uint4 u1 = bp2[(kk * 4 + 1) * 32 + lane];
            const uint4 u2 = bp2[(kk * 4 + 2) * 32 + lane];
            const uint4 u3 = bp2[(kk * 4 + 3) * 32 + lane];
            const uint32_t bv0[8] = {u0.x, u0.y, u0.z, u0.w, u1.x, u1.y, u1.z, u1.w};
            const uint32_t bv1[8] = {u2.x, u2.y, u2.z, u2.w, u3.x, u3.y, u3.z, u3.w};
#pragma unroll
            for (int nt = 0; nt < 8; nt++) {
                mma8(acc[nt][0][0], acc[nt][0][1], acc[nt][0][2], acc[nt][0][3],
                     a0[0], a0[1], a0[2], a0[3], bv0[nt], bv1[nt]);
                mma8(acc[nt][1][0], acc[nt][1][1], acc[nt][1][2], acc[nt][1][3],
                     a1[0], a1[1], a1[2], a1[3], bv0[nt], bv1[nt]);
            }
        }

        // ===== output layer (fp32): u[row] = b3 + sum_n w3[n]*tanh(acc) =====
        {
            float u0 = 0.f, u1 = 0.f, u2 = 0.f, u3 = 0.f;
#pragma unroll
            for (int nt = 0; nt < 8; nt++) {
                const float2 w3p = *(const float2*)&sm->w3[nt * 8 + 2 * t];
                u0 = fmaf(w3p.x, tanh_hw(acc[nt][0][0]), u0);
                u0 = fmaf(w3p.y, tanh_hw(acc[nt][0][1]), u0);
                u1 = fmaf(w3p.x, tanh_hw(acc[nt][0][2]), u1);
                u1 = fmaf(w3p.y, tanh_hw(acc[nt][0][3]), u1);
                u2 = fmaf(w3p.x, tanh_hw(acc[nt][1][0]), u2);
                u2 = fmaf(w3p.y, tanh_hw(acc[nt][1][1]), u2);
                u3 = fmaf(w3p.x, tanh_hw(acc[nt][1][2]), u3);
                u3 = fmaf(w3p.y, tanh_hw(acc[nt][1][3]), u3);
            }
#pragma unroll
            for (int d = 1; d < 4; d <<= 1) {
                u0 += __shfl_xor_sync(0xffffffffu, u0, d);
                u1 += __shfl_xor_sync(0xffffffffu, u1, d);
                u2 += __shfl_xor_sync(0xffffffffu, u2, d);
                u3 += __shfl_xor_sync(0xffffffffu, u3, d);
            }
            if (t == 0) {
                float* up = g_u + s * NPTS;
                if (n0 >= 0) up[n0] = u0 + b3v;
                if (n1 >= 0) up[n1] = u1 + b3v;
                if (n2 >= 0) up[n2] = u2 + b3v;
                if (n3 >= 0) up[n3] = u3 + b3v;
            }
        }
    }
}

// ---------------------------------------------------------------------------
// Reduce: Gaussian PoU over the SAME window predicate + hard-BC ansatz.
// ---------------------------------------------------------------------------
__global__ __launch_bounds__(256)
void fbpinn_reduce_kernel(const float* __restrict__ X, float* __restrict__ out) {
    const int n = blockIdx.x * 256 + threadIdx.x;
    const float x = X[n];
    const int b = bin_of(x);
    const float inv_sigma = 64.0f / 1.5f;
    float num = 0.0f, den = 0.0f;
#pragma unroll 1
    for (int s = 0; s < 64; s++) {
        int lo, hi;
        window_of(s, lo, hi);
        if (b >= lo && b <= hi) {
            float tt = (x - (float)s * (1.0f / 63.0f)) * inv_sigma;
            float r = __expf(-0.5f * tt * tt);
            num = fmaf(r, g_u[s * NPTS + n], num);
            den += r;
        }
    }
    out[n] = tanh_acc(5.0f * x) * (num / den);
}

// ---------------------------------------------------------------------------
// Inputs: x, W0, b0, W1, b1, W2, b2, W3, b3. Output fp32 [65536].
// ---------------------------------------------------------------------------
extern "C" void kernel_launch(void* const* d_in, const int* in_sizes, int n_in,
                              void* d_out, int out_size) {
    const float* X  = (const float*)d_in[0];
    const float* W0 = (const float*)d_in[1];
    const float* B0 = (const float*)d_in[2];
    const float* W1 = (const float*)d_in[3];
    const float* B1 = (const float*)d_in[4];
    const float* W2 = (const float*)d_in[5];
    const float* B2 = (const float*)d_in[6];
    const float* W3 = (const float*)d_in[7];
    const float* B3 = (const float*)d_in[8];
    float* out = (float*)d_out;

    cudaFuncSetAttribute(fbpinn_mlp, cudaFuncAttributeMaxDynamicSharedMemorySize,
                         (int)sizeof(SMem));

    const int prep_elems = 2 * NSUB * 4096;
    prep_weights<<<(prep_elems + 255) / 256, 256>>>(W1, W2);
    zero_counters<<<1, 64>>>();
    bin_points<<<NPTS / 256, 256>>>(X);
    dim3 grid(GRIDX, NSUB);
    fbpinn_mlp<<<grid, TPB, sizeof(SMem)>>>(X, W0, B0, B1, B2, W3, B3);
    fbpinn_reduce_kernel<<<NPTS / 256, 256>>>(X, out);
}